// round 1
// baseline (speedup 1.0000x reference)
#include <cuda_runtime.h>

#define BATCH 32
#define NN    512
#define FIN   256
#define FOUT  256
#define EE    2

// scratch: h[b][e][n][o]  (33.5 MB) — __device__ global, no allocation
__device__ float g_h[(size_t)BATCH * EE * NN * FOUT];

// ---------------------------------------------------------------------------
// Kernel 1: per-edge-type linear + second linear.
//   z = 0,1 : g_h[b,e=z,n,:] = X[b,n,:] @ W_adj[z] + b_adj[z]
//   z = 2   : d_out[b,n,:]   = X[b,n,:] @ W2       + b2     (lin2 staging)
// GEMM view: M = B*N = 16384, K = 256, Nout = 256. Tiles 128x128x8, 8x8/thread.
// ---------------------------------------------------------------------------
__global__ __launch_bounds__(256) void k1_linear(
    const float* __restrict__ X,
    const float* __restrict__ W_adj, const float* __restrict__ b_adj,
    const float* __restrict__ W2,    const float* __restrict__ b2,
    float* __restrict__ out_lin2)
{
    const int z = blockIdx.z;
    const float* __restrict__ W    = (z < 2) ? (W_adj + (size_t)z * FIN * FOUT) : W2;
    const float* __restrict__ bias = (z < 2) ? (b_adj + z * FOUT) : b2;

    const int mBase = blockIdx.y * 128;
    const int nBase = blockIdx.x * 128;

    __shared__ float As[8][128];
    __shared__ float Bs[8][128];

    const int tid  = threadIdx.x;
    const int tRow = (tid >> 4) * 8;   // 0..120
    const int tCol = (tid & 15) * 8;   // 0..120

    // loader mapping
    const int aRow = tid >> 1;         // 0..127
    const int aCol = (tid & 1) * 4;    // 0 or 4
    const int bRow = tid >> 5;         // 0..7
    const int bCol = (tid & 31) * 4;   // 0..124

    float acc[8][8];
    #pragma unroll
    for (int i = 0; i < 8; i++)
        #pragma unroll
        for (int j = 0; j < 8; j++) acc[i][j] = 0.f;

    const float* Aptr = X + (size_t)(mBase + aRow) * FIN + aCol;
    const float* Bptr = W + (size_t)bRow * FOUT + nBase + bCol;

    for (int k0 = 0; k0 < FIN; k0 += 8) {
        float4 a = *(const float4*)(Aptr + k0);
        As[aCol + 0][aRow] = a.x;
        As[aCol + 1][aRow] = a.y;
        As[aCol + 2][aRow] = a.z;
        As[aCol + 3][aRow] = a.w;
        *(float4*)(&Bs[bRow][bCol]) = *(const float4*)(Bptr + (size_t)k0 * FOUT);
        __syncthreads();
        #pragma unroll
        for (int k = 0; k < 8; k++) {
            float4 ra0 = *(const float4*)(&As[k][tRow]);
            float4 ra1 = *(const float4*)(&As[k][tRow + 4]);
            float4 rb0 = *(const float4*)(&Bs[k][tCol]);
            float4 rb1 = *(const float4*)(&Bs[k][tCol + 4]);
            float ra[8] = {ra0.x, ra0.y, ra0.z, ra0.w, ra1.x, ra1.y, ra1.z, ra1.w};
            float rb[8] = {rb0.x, rb0.y, rb0.z, rb0.w, rb1.x, rb1.y, rb1.z, rb1.w};
            #pragma unroll
            for (int i = 0; i < 8; i++)
                #pragma unroll
                for (int j = 0; j < 8; j++)
                    acc[i][j] += ra[i] * rb[j];
        }
        __syncthreads();
    }

    // epilogue: add bias, write to g_h (z<2) or out_lin2 (z==2)
    #pragma unroll
    for (int i = 0; i < 8; i++) {
        const int m = mBase + tRow + i;       // flat row in [0, B*N)
        const int b = m >> 9;                 // /512
        const int n = m & 511;
        #pragma unroll
        for (int j = 0; j < 8; j += 4) {
            const int o = nBase + tCol + j;
            float4 v;
            v.x = acc[i][j + 0] + bias[o + 0];
            v.y = acc[i][j + 1] + bias[o + 1];
            v.z = acc[i][j + 2] + bias[o + 2];
            v.w = acc[i][j + 3] + bias[o + 3];
            if (z < 2) {
                *(float4*)(&g_h[(((size_t)b * EE + z) * NN + n) * FOUT + o]) = v;
            } else {
                *(float4*)(&out_lin2[(size_t)m * FOUT + o]) = v;
            }
        }
    }
}

// ---------------------------------------------------------------------------
// Kernel 2: per batch b:
//   out[b,m,o] = relu( sum_e adj[b,e,m,:] @ g_h[b,e,:,o]  +  out[b,m,o] )
// (out currently holds lin2 from kernel 1). GEMM M=512, Nout=256, K=512 x2.
// ---------------------------------------------------------------------------
__global__ __launch_bounds__(256) void k2_agg(
    const float* __restrict__ adj,
    float* __restrict__ out)
{
    const int b     = blockIdx.z;
    const int mBase = blockIdx.y * 128;  // within N=512
    const int nBase = blockIdx.x * 128;  // within FOUT=256

    __shared__ float As[8][128];
    __shared__ float Bs[8][128];

    const int tid  = threadIdx.x;
    const int tRow = (tid >> 4) * 8;
    const int tCol = (tid & 15) * 8;

    const int aRow = tid >> 1;
    const int aCol = (tid & 1) * 4;
    const int bRow = tid >> 5;
    const int bCol = (tid & 31) * 4;

    float acc[8][8];
    #pragma unroll
    for (int i = 0; i < 8; i++)
        #pragma unroll
        for (int j = 0; j < 8; j++) acc[i][j] = 0.f;

    for (int e = 0; e < EE; e++) {
        const float* __restrict__ A  = adj + ((size_t)(b * EE + e) * NN) * NN;   // [512,512]
        const float* __restrict__ Bm = g_h + (size_t)(b * EE + e) * NN * FOUT;   // [512,256]
        const float* Aptr = A  + (size_t)(mBase + aRow) * NN + aCol;
        const float* Bptr = Bm + (size_t)bRow * FOUT + nBase + bCol;

        for (int k0 = 0; k0 < NN; k0 += 8) {
            float4 a = *(const float4*)(Aptr + k0);
            As[aCol + 0][aRow] = a.x;
            As[aCol + 1][aRow] = a.y;
            As[aCol + 2][aRow] = a.z;
            As[aCol + 3][aRow] = a.w;
            *(float4*)(&Bs[bRow][bCol]) = *(const float4*)(Bptr + (size_t)k0 * FOUT);
            __syncthreads();
            #pragma unroll
            for (int k = 0; k < 8; k++) {
                float4 ra0 = *(const float4*)(&As[k][tRow]);
                float4 ra1 = *(const float4*)(&As[k][tRow + 4]);
                float4 rb0 = *(const float4*)(&Bs[k][tCol]);
                float4 rb1 = *(const float4*)(&Bs[k][tCol + 4]);
                float ra[8] = {ra0.x, ra0.y, ra0.z, ra0.w, ra1.x, ra1.y, ra1.z, ra1.w};
                float rb[8] = {rb0.x, rb0.y, rb0.z, rb0.w, rb1.x, rb1.y, rb1.z, rb1.w};
                #pragma unroll
                for (int i = 0; i < 8; i++)
                    #pragma unroll
                    for (int j = 0; j < 8; j++)
                        acc[i][j] += ra[i] * rb[j];
            }
            __syncthreads();
        }
    }

    // epilogue: add lin2 (already in out), relu, write back
    #pragma unroll
    for (int i = 0; i < 8; i++) {
        const int m = mBase + tRow + i;
        #pragma unroll
        for (int j = 0; j < 8; j += 4) {
            const int o = nBase + tCol + j;
            const size_t idx = ((size_t)b * NN + m) * FOUT + o;
            float4 l = *(const float4*)(&out[idx]);
            float4 v;
            v.x = acc[i][j + 0] + l.x;
            v.y = acc[i][j + 1] + l.y;
            v.z = acc[i][j + 2] + l.z;
            v.w = acc[i][j + 3] + l.w;
            v.x = v.x > 0.f ? v.x : 0.f;
            v.y = v.y > 0.f ? v.y : 0.f;
            v.z = v.z > 0.f ? v.z : 0.f;
            v.w = v.w > 0.f ? v.w : 0.f;
            *(float4*)(&out[idx]) = v;
        }
    }
}

extern "C" void kernel_launch(void* const* d_in, const int* in_sizes, int n_in,
                              void* d_out, int out_size)
{
    const float* n_tensor   = (const float*)d_in[0];  // [32,512,256]
    const float* adj_tensor = (const float*)d_in[1];  // [32,2,512,512]
    const float* W_adj      = (const float*)d_in[2];  // [2,256,256]
    const float* b_adj      = (const float*)d_in[3];  // [2,256]
    const float* W2         = (const float*)d_in[4];  // [256,256]
    const float* b2         = (const float*)d_in[5];  // [256]
    float*       out        = (float*)d_out;          // [32,512,256]

    // K1: M=B*N=16384 -> 128 row tiles; Nout=256 -> 2 col tiles; z: 2 edges + lin2
    dim3 grid1(FOUT / 128, (BATCH * NN) / 128, 3);
    k1_linear<<<grid1, 256>>>(n_tensor, W_adj, b_adj, W2, b2, out);

    // K2: per batch, M=512 -> 4 tiles, Nout=256 -> 2 tiles
    dim3 grid2(FOUT / 128, NN / 128, BATCH);
    k2_agg<<<grid2, 256>>>(adj_tensor, out);
}

// round 3
// speedup vs baseline: 3.1728x; 3.1728x over previous
#include <cuda_runtime.h>
#include <cstdint>

#define BATCH 32
#define NN    512
#define FIN   256
#define FOUT  256
#define EE    2

#define BK      32
#define LDS_    36                        // 32 + 4 pad (floats)
#define TILE_F  (128 * LDS_)              // floats per operand tile
#define STAGE_F (2 * TILE_F)
#define NSTAGE  3
#define SMEM_BYTES (NSTAGE * STAGE_F * 4) // 110592 B

// scratch (no allocation allowed)
__device__ float g_hT[(size_t)BATCH * EE * FOUT * NN];  // [b][e][o][n]
__device__ float g_WT[3 * FIN * FOUT];                  // z=0,1: W_adj^T [o][f]; z=2: W2^T

// ---------------------------------------------------------------- helpers ---
__device__ __forceinline__ uint32_t smem_u32(const void* p) {
    uint32_t a;
    asm("{ .reg .u64 t; cvta.to.shared.u64 t, %1; cvt.u32.u64 %0, t; }" : "=r"(a) : "l"(p));
    return a;
}
__device__ __forceinline__ uint32_t to_tf32(float x) {
    uint32_t u;
    asm("cvt.rna.tf32.f32 %0, %1;" : "=r"(u) : "f"(x));
    return u;
}
__device__ __forceinline__ void mma_tf32(float* d,
    uint32_t a0, uint32_t a1, uint32_t a2, uint32_t a3, uint32_t b0, uint32_t b1) {
    asm volatile(
        "mma.sync.aligned.m16n8k8.row.col.f32.tf32.tf32.f32 "
        "{%0,%1,%2,%3}, {%4,%5,%6,%7}, {%8,%9}, {%0,%1,%2,%3};"
        : "+f"(d[0]), "+f"(d[1]), "+f"(d[2]), "+f"(d[3])
        : "r"(a0), "r"(a1), "r"(a2), "r"(a3), "r"(b0), "r"(b1));
}
#define CP_COMMIT() asm volatile("cp.async.commit_group;" ::: "memory")
#define CP_WAIT2()  asm volatile("cp.async.wait_group 2;" ::: "memory")

// cooperative async copy of one 128x32f tile into padded smem (stride 36)
__device__ __forceinline__ void load_tile(const float* __restrict__ g, int ld,
                                          float* s, int tid) {
    #pragma unroll
    for (int i = 0; i < 4; i++) {
        int idx = i * 256 + tid, r = idx >> 3, c = idx & 7;
        uint32_t dst = smem_u32(s + r * LDS_ + c * 4);
        const float* src = g + (size_t)r * ld + c * 4;
        asm volatile("cp.async.cg.shared.global [%0], [%1], 16;" :: "r"(dst), "l"(src) : "memory");
    }
}

// one BK=32 chunk of the 128x128 warp-tiled mma (warp tile 64x32)
__device__ __forceinline__ void compute_chunk(const float* __restrict__ As,
                                              const float* __restrict__ Bs,
                                              int wm, int wn, int lane,
                                              float acc[4][4][4]) {
    const int g = lane >> 2, t = lane & 3;
    #pragma unroll
    for (int ks = 0; ks < 4; ks++) {
        const int k0 = ks * 8;
        uint32_t af[4][4];
        #pragma unroll
        for (int mf = 0; mf < 4; mf++) {
            int r = wm * 64 + mf * 16 + g;
            const float* p0 = As + r * LDS_ + k0 + t;
            const float* p1 = As + (r + 8) * LDS_ + k0 + t;
            af[mf][0] = to_tf32(p0[0]);
            af[mf][1] = to_tf32(p1[0]);
            af[mf][2] = to_tf32(p0[4]);
            af[mf][3] = to_tf32(p1[4]);
        }
        uint32_t bf[4][2];
        #pragma unroll
        for (int nf = 0; nf < 4; nf++) {
            int r = wn * 32 + nf * 8 + g;
            const float* p = Bs + r * LDS_ + k0 + t;
            bf[nf][0] = to_tf32(p[0]);
            bf[nf][1] = to_tf32(p[4]);
        }
        #pragma unroll
        for (int mf = 0; mf < 4; mf++)
            #pragma unroll
            for (int nf = 0; nf < 4; nf++)
                mma_tf32(acc[mf][nf], af[mf][0], af[mf][1], af[mf][2], af[mf][3],
                         bf[nf][0], bf[nf][1]);
    }
}

// ---------------------------------------------------------------------------
// k0: W transposes into g_WT  ([f][o] -> [o][f])
// ---------------------------------------------------------------------------
__global__ void k0_transpose(const float* __restrict__ W_adj, const float* __restrict__ W2)
{
    __shared__ float t[32][33];
    int z = blockIdx.z;
    const float* src = (z < 2) ? (W_adj + (size_t)z * FIN * FOUT) : W2;
    int bo = blockIdx.x * 32, bf = blockIdx.y * 32;
    int tx = threadIdx.x, ty = threadIdx.y;
    #pragma unroll
    for (int j = 0; j < 32; j += 8) t[ty + j][tx] = src[(size_t)(bf + ty + j) * FOUT + bo + tx];
    __syncthreads();
    float* dst = g_WT + (size_t)z * FIN * FOUT;
    #pragma unroll
    for (int j = 0; j < 32; j += 8) dst[(size_t)(bo + ty + j) * FIN + bf + tx] = t[tx][ty + j];
}

// ---------------------------------------------------------------------------
// k1: hT[b,e,o,n] = sum_f WT_e[o,f] * X[b,n,f] + b_adj[e,o]
//     CTA tile: M=128 (o), N=128 (n), K=256 (8 chunks)
// ---------------------------------------------------------------------------
__global__ __launch_bounds__(256, 1) void k1_ht(
    const float* __restrict__ X, const float* __restrict__ b_adj)
{
    extern __shared__ float sm[];
    const int tid = threadIdx.x, lane = tid & 31, wid = tid >> 5;
    const int wm = wid & 1, wn = wid >> 1;
    const int o0 = (blockIdx.x & 1) * 128, n0 = (blockIdx.x >> 1) * 128;
    const int b = blockIdx.y, e = blockIdx.z;

    const float* A  = g_WT + (size_t)e * FIN * FOUT + (size_t)o0 * FIN;
    const float* Bm = X + ((size_t)b * NN + n0) * FIN;

    float acc[4][4][4];
    #pragma unroll
    for (int i = 0; i < 4; i++)
        #pragma unroll
        for (int j = 0; j < 4; j++)
            #pragma unroll
            for (int q = 0; q < 4; q++) acc[i][j][q] = 0.f;

    const int C = 8;
    load_tile(A, FIN, sm, tid);
    load_tile(Bm, FIN, sm + TILE_F, tid);
    CP_COMMIT();
    load_tile(A + BK, FIN, sm + STAGE_F, tid);
    load_tile(Bm + BK, FIN, sm + STAGE_F + TILE_F, tid);
    CP_COMMIT();

    for (int c = 0; c < C; c++) {
        if (c + 2 < C) {
            int s2 = (c + 2) % NSTAGE;
            load_tile(A + (c + 2) * BK, FIN, sm + s2 * STAGE_F, tid);
            load_tile(Bm + (c + 2) * BK, FIN, sm + s2 * STAGE_F + TILE_F, tid);
        }
        CP_COMMIT();
        CP_WAIT2();
        __syncthreads();
        const float* st = sm + (c % NSTAGE) * STAGE_F;
        compute_chunk(st, st + TILE_F, wm, wn, lane, acc);
        __syncthreads();
    }

    // epilogue: + b_adj[e,o] (row-dependent), store to g_hT
    const int g = lane >> 2, t = lane & 3;
    #pragma unroll
    for (int mf = 0; mf < 4; mf++) {
        int r0 = o0 + wm * 64 + mf * 16 + g;
        float bias0 = b_adj[e * FOUT + r0];
        float bias1 = b_adj[e * FOUT + r0 + 8];
        #pragma unroll
        for (int nf = 0; nf < 4; nf++) {
            int cc = n0 + wn * 32 + nf * 8 + 2 * t;
            float* d0 = g_hT + (((size_t)(b * EE + e) * FOUT) + r0) * NN + cc;
            float* d1 = g_hT + (((size_t)(b * EE + e) * FOUT) + r0 + 8) * NN + cc;
            float2 v0 = make_float2(acc[mf][nf][0] + bias0, acc[mf][nf][1] + bias0);
            float2 v1 = make_float2(acc[mf][nf][2] + bias1, acc[mf][nf][3] + bias1);
            *(float2*)d0 = v0;
            *(float2*)d1 = v1;
        }
    }
}

// ---------------------------------------------------------------------------
// k2: out[b,m,o] = relu( sum_e adj[b,e,m,:] . hT[b,e,o,:]
//                      + X[b,m,:] . W2T[o,:] + b2[o] )
//     CTA tile: M=128 (m), N=128 (o); 40 chained K-chunks
// ---------------------------------------------------------------------------
__global__ __launch_bounds__(256, 1) void k2_main(
    const float* __restrict__ adj, const float* __restrict__ X,
    const float* __restrict__ b2, float* __restrict__ out)
{
    extern __shared__ float sm[];
    const int tid = threadIdx.x, lane = tid & 31, wid = tid >> 5;
    const int wm = wid & 1, wn = wid >> 1;
    const int m0 = (blockIdx.x >> 1) * 128, o0 = (blockIdx.x & 1) * 128;
    const int b = blockIdx.y;

    const float* adjb = adj + (size_t)b * EE * NN * NN + (size_t)m0 * NN;
    const float* hTb  = g_hT + (size_t)b * EE * FOUT * NN + (size_t)o0 * NN;
    const float* Xb   = X + ((size_t)b * NN + m0) * FIN;
    const float* W2T  = g_WT + (size_t)2 * FIN * FOUT + (size_t)o0 * FIN;

    float acc[4][4][4];
    #pragma unroll
    for (int i = 0; i < 4; i++)
        #pragma unroll
        for (int j = 0; j < 4; j++)
            #pragma unroll
            for (int q = 0; q < 4; q++) acc[i][j][q] = 0.f;

    const int C = 40;  // 16 (e=0) + 16 (e=1) + 8 (lin2)
    #define CHUNK_PTRS(c, Ab, ldA, Bb, ldB)                                 \
        const float* Ab; const float* Bb; int ldA, ldB;                     \
        if ((c) < 32) {                                                     \
            int e_ = (c) >> 4, kc_ = (c) & 15;                              \
            Ab = adjb + (size_t)e_ * NN * NN + kc_ * BK;   ldA = NN;        \
            Bb = hTb  + (size_t)e_ * FOUT * NN + kc_ * BK; ldB = NN;        \
        } else {                                                            \
            int kc_ = (c) - 32;                                             \
            Ab = Xb  + kc_ * BK;  ldA = FIN;                                \
            Bb = W2T + kc_ * BK;  ldB = FIN;                                \
        }

    {
        CHUNK_PTRS(0, Ab, ldA, Bb, ldB);
        load_tile(Ab, ldA, sm, tid);
        load_tile(Bb, ldB, sm + TILE_F, tid);
        CP_COMMIT();
    }
    {
        CHUNK_PTRS(1, Ab, ldA, Bb, ldB);
        load_tile(Ab, ldA, sm + STAGE_F, tid);
        load_tile(Bb, ldB, sm + STAGE_F + TILE_F, tid);
        CP_COMMIT();
    }

    for (int c = 0; c < C; c++) {
        if (c + 2 < C) {
            int s2 = (c + 2) % NSTAGE;
            CHUNK_PTRS(c + 2, Ab, ldA, Bb, ldB);
            load_tile(Ab, ldA, sm + s2 * STAGE_F, tid);
            load_tile(Bb, ldB, sm + s2 * STAGE_F + TILE_F, tid);
        }
        CP_COMMIT();
        CP_WAIT2();
        __syncthreads();
        const float* st = sm + (c % NSTAGE) * STAGE_F;
        compute_chunk(st, st + TILE_F, wm, wn, lane, acc);
        __syncthreads();
    }

    // epilogue: + b2[o] (col-dependent), relu, store
    const int g = lane >> 2, t = lane & 3;
    #pragma unroll
    for (int mf = 0; mf < 4; mf++) {
        int r0 = m0 + wm * 64 + mf * 16 + g;
        #pragma unroll
        for (int nf = 0; nf < 4; nf++) {
            int cc = o0 + wn * 32 + nf * 8 + 2 * t;
            float bx = b2[cc], by = b2[cc + 1];
            float* d0 = out + ((size_t)b * NN + r0) * FOUT + cc;
            float* d1 = out + ((size_t)b * NN + r0 + 8) * FOUT + cc;
            float2 v0 = make_float2(fmaxf(acc[mf][nf][0] + bx, 0.f),
                                    fmaxf(acc[mf][nf][1] + by, 0.f));
            float2 v1 = make_float2(fmaxf(acc[mf][nf][2] + bx, 0.f),
                                    fmaxf(acc[mf][nf][3] + by, 0.f));
            *(float2*)d0 = v0;
            *(float2*)d1 = v1;
        }
    }
}

// ---------------------------------------------------------------------------
extern "C" void kernel_launch(void* const* d_in, const int* in_sizes, int n_in,
                              void* d_out, int out_size)
{
    const float* n_tensor   = (const float*)d_in[0];  // [32,512,256]
    const float* adj_tensor = (const float*)d_in[1];  // [32,2,512,512]
    const float* W_adj      = (const float*)d_in[2];  // [2,256,256]
    const float* b_adj      = (const float*)d_in[3];  // [2,256]
    const float* W2         = (const float*)d_in[4];  // [256,256]
    const float* b2         = (const float*)d_in[5];  // [256]
    float*       out        = (float*)d_out;          // [32,512,256]

    cudaFuncSetAttribute(k1_ht,   cudaFuncAttributeMaxDynamicSharedMemorySize, SMEM_BYTES);
    cudaFuncSetAttribute(k2_main, cudaFuncAttributeMaxDynamicSharedMemorySize, SMEM_BYTES);

    k0_transpose<<<dim3(8, 8, 3), dim3(32, 8)>>>(W_adj, W2);
    k1_ht<<<dim3(8, BATCH, EE), 256, SMEM_BYTES>>>(n_tensor, b_adj);
    k2_main<<<dim3(8, BATCH), 256, SMEM_BYTES>>>(adj_tensor, n_tensor, b2, out);
}

// round 4
// speedup vs baseline: 3.1736x; 1.0002x over previous
#include <cuda_runtime.h>
#include <cstdint>

#define BATCH 32
#define NN    512
#define FIN   256
#define FOUT  256
#define EE    2

#define BK      32
#define LDS_    36                        // 32 + 4 pad (floats)
#define TILE_F  (128 * LDS_)              // floats per operand tile
#define STAGE_F (2 * TILE_F)
#define NSTAGE  3
#define SMEM_BYTES (NSTAGE * STAGE_F * 4) // 110592 B -> 2 CTAs/SM (221KB < 228KB)

// scratch (no allocation allowed)
__device__ float g_hT[(size_t)BATCH * EE * FOUT * NN];  // [b][e][o][n]  (tf32-pre-rounded)
__device__ float g_WT[3 * FIN * FOUT];                  // z=0,1: W_adj^T; z=2: W2^T (tf32-pre-rounded)

// ---------------------------------------------------------------- helpers ---
__device__ __forceinline__ uint32_t smem_u32(const void* p) {
    uint32_t a;
    asm("{ .reg .u64 t; cvta.to.shared.u64 t, %1; cvt.u32.u64 %0, t; }" : "=r"(a) : "l"(p));
    return a;
}
__device__ __forceinline__ uint32_t to_tf32(float x) {
    uint32_t u;
    asm("cvt.rna.tf32.f32 %0, %1;" : "=r"(u) : "f"(x));
    return u;
}
__device__ __forceinline__ float round_tf32(float x) {
    return __uint_as_float(to_tf32(x));
}
__device__ __forceinline__ void mma_tf32(float* d,
    uint32_t a0, uint32_t a1, uint32_t a2, uint32_t a3, uint32_t b0, uint32_t b1) {
    asm volatile(
        "mma.sync.aligned.m16n8k8.row.col.f32.tf32.tf32.f32 "
        "{%0,%1,%2,%3}, {%4,%5,%6,%7}, {%8,%9}, {%0,%1,%2,%3};"
        : "+f"(d[0]), "+f"(d[1]), "+f"(d[2]), "+f"(d[3])
        : "r"(a0), "r"(a1), "r"(a2), "r"(a3), "r"(b0), "r"(b1));
}
#define CP_COMMIT() asm volatile("cp.async.commit_group;" ::: "memory")
#define CP_WAIT1()  asm volatile("cp.async.wait_group 1;" ::: "memory")

// cooperative async copy of one 128x32f tile into padded smem (stride 36)
__device__ __forceinline__ void load_tile(const float* __restrict__ g, int ld,
                                          float* s, int tid) {
    #pragma unroll
    for (int i = 0; i < 4; i++) {
        int idx = i * 256 + tid, r = idx >> 3, c = idx & 7;
        uint32_t dst = smem_u32(s + r * LDS_ + c * 4);
        const float* src = g + (size_t)r * ld + c * 4;
        asm volatile("cp.async.cg.shared.global [%0], [%1], 16;" :: "r"(dst), "l"(src) : "memory");
    }
}

// one BK=32 chunk of the 128x128 warp-tiled mma (warp tile 64x32)
template<bool CVT_A, bool CVT_B>
__device__ __forceinline__ void compute_chunk(const float* __restrict__ As,
                                              const float* __restrict__ Bs,
                                              int wm, int wn, int lane,
                                              float acc[4][4][4]) {
    const int g = lane >> 2, t = lane & 3;
    #pragma unroll
    for (int ks = 0; ks < 4; ks++) {
        const int k0 = ks * 8;
        uint32_t af[4][4];
        #pragma unroll
        for (int mf = 0; mf < 4; mf++) {
            int r = wm * 64 + mf * 16 + g;
            const float* p0 = As + r * LDS_ + k0 + t;
            const float* p1 = As + (r + 8) * LDS_ + k0 + t;
            if (CVT_A) {
                af[mf][0] = to_tf32(p0[0]); af[mf][1] = to_tf32(p1[0]);
                af[mf][2] = to_tf32(p0[4]); af[mf][3] = to_tf32(p1[4]);
            } else {
                af[mf][0] = __float_as_uint(p0[0]); af[mf][1] = __float_as_uint(p1[0]);
                af[mf][2] = __float_as_uint(p0[4]); af[mf][3] = __float_as_uint(p1[4]);
            }
        }
        uint32_t bf[4][2];
        #pragma unroll
        for (int nf = 0; nf < 4; nf++) {
            int r = wn * 32 + nf * 8 + g;
            const float* p = Bs + r * LDS_ + k0 + t;
            if (CVT_B) { bf[nf][0] = to_tf32(p[0]); bf[nf][1] = to_tf32(p[4]); }
            else       { bf[nf][0] = __float_as_uint(p[0]); bf[nf][1] = __float_as_uint(p[4]); }
        }
        #pragma unroll
        for (int mf = 0; mf < 4; mf++)
            #pragma unroll
            for (int nf = 0; nf < 4; nf++)
                mma_tf32(acc[mf][nf], af[mf][0], af[mf][1], af[mf][2], af[mf][3],
                         bf[nf][0], bf[nf][1]);
    }
}

__device__ __forceinline__ void zero_acc(float acc[4][4][4]) {
    #pragma unroll
    for (int i = 0; i < 4; i++)
        #pragma unroll
        for (int j = 0; j < 4; j++)
            #pragma unroll
            for (int q = 0; q < 4; q++) acc[i][j][q] = 0.f;
}

// ---------------------------------------------------------------------------
// k0: W transposes into g_WT  ([f][o] -> [o][f]), tf32-pre-rounded
// ---------------------------------------------------------------------------
__global__ void k0_transpose(const float* __restrict__ W_adj, const float* __restrict__ W2)
{
    __shared__ float t[32][33];
    int z = blockIdx.z;
    const float* src = (z < 2) ? (W_adj + (size_t)z * FIN * FOUT) : W2;
    int bo = blockIdx.x * 32, bf = blockIdx.y * 32;
    int tx = threadIdx.x, ty = threadIdx.y;
    #pragma unroll
    for (int j = 0; j < 32; j += 8) t[ty + j][tx] = src[(size_t)(bf + ty + j) * FOUT + bo + tx];
    __syncthreads();
    float* dst = g_WT + (size_t)z * FIN * FOUT;
    #pragma unroll
    for (int j = 0; j < 32; j += 8)
        dst[(size_t)(bo + ty + j) * FIN + bf + tx] = round_tf32(t[tx][ty + j]);
}

// ---------------------------------------------------------------------------
// k1: hT[b,e,o,n] = sum_f WT_e[o,f] * X[b,n,f] + b_adj[e,o]   (both e in one CTA)
//     CTA tile: M=128 (o), N=128 (n); 16 chunks (8 per e)
// ---------------------------------------------------------------------------
__global__ __launch_bounds__(256, 2) void k1_ht(
    const float* __restrict__ X, const float* __restrict__ b_adj)
{
    extern __shared__ float sm[];
    const int tid = threadIdx.x, lane = tid & 31, wid = tid >> 5;
    const int wm = wid & 1, wn = wid >> 1;
    const int o0 = (blockIdx.x & 1) * 128, n0 = (blockIdx.x >> 1) * 128;
    const int b = blockIdx.y;

    const float* Bm = X + ((size_t)b * NN + n0) * FIN;

    float acc[4][4][4];
    zero_acc(acc);

    const int C = 16;
    #define K1_A(c) (g_WT + (size_t)((c) >> 3) * FIN * FOUT + (size_t)o0 * FIN + ((c) & 7) * BK)
    #define K1_B(c) (Bm + ((c) & 7) * BK)

    load_tile(K1_A(0), FIN, sm, tid);
    load_tile(K1_B(0), FIN, sm + TILE_F, tid);
    CP_COMMIT();
    load_tile(K1_A(1), FIN, sm + STAGE_F, tid);
    load_tile(K1_B(1), FIN, sm + STAGE_F + TILE_F, tid);
    CP_COMMIT();

    const int g = lane >> 2, t = lane & 3;
    for (int c = 0; c < C; c++) {
        CP_WAIT1();
        __syncthreads();
        if (c + 2 < C) {
            int s2 = (c + 2) % NSTAGE;
            load_tile(K1_A(c + 2), FIN, sm + s2 * STAGE_F, tid);
            load_tile(K1_B(c + 2), FIN, sm + s2 * STAGE_F + TILE_F, tid);
        }
        CP_COMMIT();
        const float* st = sm + (c % NSTAGE) * STAGE_F;
        compute_chunk<false, true>(st, st + TILE_F, wm, wn, lane, acc);

        if ((c & 7) == 7) {
            // epilogue for edge type e = c>>3: +bias, tf32-round, store, reset
            int e = c >> 3;
            #pragma unroll
            for (int mf = 0; mf < 4; mf++) {
                int r0 = o0 + wm * 64 + mf * 16 + g;
                float bias0 = b_adj[e * FOUT + r0];
                float bias1 = b_adj[e * FOUT + r0 + 8];
                #pragma unroll
                for (int nf = 0; nf < 4; nf++) {
                    int cc = n0 + wn * 32 + nf * 8 + 2 * t;
                    float* d0 = g_hT + (((size_t)(b * EE + e) * FOUT) + r0) * NN + cc;
                    float* d1 = g_hT + (((size_t)(b * EE + e) * FOUT) + r0 + 8) * NN + cc;
                    float2 v0 = make_float2(round_tf32(acc[mf][nf][0] + bias0),
                                            round_tf32(acc[mf][nf][1] + bias0));
                    float2 v1 = make_float2(round_tf32(acc[mf][nf][2] + bias1),
                                            round_tf32(acc[mf][nf][3] + bias1));
                    *(float2*)d0 = v0;
                    *(float2*)d1 = v1;
                }
            }
            zero_acc(acc);
        }
    }
}

// ---------------------------------------------------------------------------
// k2: out[b,m,o] = relu( sum_e adj[b,e,m,:] . hT[b,e,o,:]
//                      + X[b,m,:] . W2T[o,:] + b2[o] )
//     CTA tile: M=128 (m), N=128 (o); 40 chained K-chunks
// ---------------------------------------------------------------------------
__global__ __launch_bounds__(256, 2) void k2_main(
    const float* __restrict__ adj, const float* __restrict__ X,
    const float* __restrict__ b2, float* __restrict__ out)
{
    extern __shared__ float sm[];
    const int tid = threadIdx.x, lane = tid & 31, wid = tid >> 5;
    const int wm = wid & 1, wn = wid >> 1;
    const int m0 = (blockIdx.x >> 1) * 128, o0 = (blockIdx.x & 1) * 128;
    const int b = blockIdx.y;

    const float* adjb = adj + (size_t)b * EE * NN * NN + (size_t)m0 * NN;
    const float* hTb  = g_hT + (size_t)b * EE * FOUT * NN + (size_t)o0 * NN;
    const float* Xb   = X + ((size_t)b * NN + m0) * FIN;
    const float* W2T  = g_WT + (size_t)2 * FIN * FOUT + (size_t)o0 * FIN;

    float acc[4][4][4];
    zero_acc(acc);

    const int C = 40;  // 16 (e=0) + 16 (e=1) + 8 (lin2)
    #define CHUNK_PTRS(c, Ab, ldA, Bb, ldB)                                 \
        const float* Ab; const float* Bb; int ldA, ldB;                     \
        if ((c) < 32) {                                                     \
            int e_ = (c) >> 4, kc_ = (c) & 15;                              \
            Ab = adjb + (size_t)e_ * NN * NN + kc_ * BK;   ldA = NN;        \
            Bb = hTb  + (size_t)e_ * FOUT * NN + kc_ * BK; ldB = NN;        \
        } else {                                                            \
            int kc_ = (c) - 32;                                             \
            Ab = Xb  + kc_ * BK;  ldA = FIN;                                \
            Bb = W2T + kc_ * BK;  ldB = FIN;                                \
        }

    {
        CHUNK_PTRS(0, Ab, ldA, Bb, ldB);
        load_tile(Ab, ldA, sm, tid);
        load_tile(Bb, ldB, sm + TILE_F, tid);
        CP_COMMIT();
    }
    {
        CHUNK_PTRS(1, Ab, ldA, Bb, ldB);
        load_tile(Ab, ldA, sm + STAGE_F, tid);
        load_tile(Bb, ldB, sm + STAGE_F + TILE_F, tid);
        CP_COMMIT();
    }

    for (int c = 0; c < C; c++) {
        CP_WAIT1();
        __syncthreads();
        if (c + 2 < C) {
            int s2 = (c + 2) % NSTAGE;
            CHUNK_PTRS(c + 2, Ab, ldA, Bb, ldB);
            load_tile(Ab, ldA, sm + s2 * STAGE_F, tid);
            load_tile(Bb, ldB, sm + s2 * STAGE_F + TILE_F, tid);
        }
        CP_COMMIT();
        const float* st = sm + (c % NSTAGE) * STAGE_F;
        // A (adj/X) needs rna-cvt; B (hT/W2T) is pre-rounded
        compute_chunk<true, false>(st, st + TILE_F, wm, wn, lane, acc);
    }

    // epilogue: + b2[o] (col-dependent), relu, store
    const int g = lane >> 2, t = lane & 3;
    #pragma unroll
    for (int mf = 0; mf < 4; mf++) {
        int r0 = m0 + wm * 64 + mf * 16 + g;
        #pragma unroll
        for (int nf = 0; nf < 4; nf++) {
            int cc = o0 + wn * 32 + nf * 8 + 2 * t;
            float bx = b2[cc], by = b2[cc + 1];
            float* d0 = out + ((size_t)b * NN + r0) * FOUT + cc;
            float* d1 = out + ((size_t)b * NN + r0 + 8) * FOUT + cc;
            float2 v0 = make_float2(fmaxf(acc[mf][nf][0] + bx, 0.f),
                                    fmaxf(acc[mf][nf][1] + by, 0.f));
            float2 v1 = make_float2(fmaxf(acc[mf][nf][2] + bx, 0.f),
                                    fmaxf(acc[mf][nf][3] + by, 0.f));
            *(float2*)d0 = v0;
            *(float2*)d1 = v1;
        }
    }
}

// ---------------------------------------------------------------------------
extern "C" void kernel_launch(void* const* d_in, const int* in_sizes, int n_in,
                              void* d_out, int out_size)
{
    const float* n_tensor   = (const float*)d_in[0];  // [32,512,256]
    const float* adj_tensor = (const float*)d_in[1];  // [32,2,512,512]
    const float* W_adj      = (const float*)d_in[2];  // [2,256,256]
    const float* b_adj      = (const float*)d_in[3];  // [2,256]
    const float* W2         = (const float*)d_in[4];  // [256,256]
    const float* b2         = (const float*)d_in[5];  // [256]
    float*       out        = (float*)d_out;          // [32,512,256]

    cudaFuncSetAttribute(k1_ht,   cudaFuncAttributeMaxDynamicSharedMemorySize, SMEM_BYTES);
    cudaFuncSetAttribute(k2_main, cudaFuncAttributeMaxDynamicSharedMemorySize, SMEM_BYTES);

    k0_transpose<<<dim3(8, 8, 3), dim3(32, 8)>>>(W_adj, W2);
    k1_ht<<<dim3(8, BATCH), 256, SMEM_BYTES>>>(n_tensor, b_adj);
    k2_main<<<dim3(8, BATCH), 256, SMEM_BYTES>>>(adj_tensor, n_tensor, b2, out);
}

// round 5
// speedup vs baseline: 3.3848x; 1.0665x over previous
#include <cuda_runtime.h>
#include <cstdint>

#define BATCH 32
#define NN    512
#define FIN   256
#define FOUT  256
#define EE    2

#define BK      32
#define LDN     36                         // padded stride: normal K-major tiles (floats)
#define LDT1    136                        // padded stride: transposed W tile (k1), 136%32==8
#define LDT2    264                        // padded stride: transposed W2 tile (k2), 264%32==8

// per-stage float counts
#define K1_AF   (32 * LDT1)                // 4352
#define K1_BF   (256 * LDN)                // 9216
#define K1_STAGE (K1_AF + K1_BF)           // 13568 floats = 54272 B
#define K2_AF   (128 * LDN)                // 4608
#define K2_BF   (256 * LDN)                // 9216  (>= 32*LDT2 = 8448)
#define K2_STAGE (K2_AF + K2_BF)           // 13824 floats = 55296 B

#define NSTAGE  3
#define K1_SMEM (NSTAGE * K1_STAGE * 4)    // 162816 B
#define K2_SMEM (NSTAGE * K2_STAGE * 4)    // 165888 B

// scratch (no allocation allowed): hT[b][e][o][n], tf32-pre-rounded
__device__ float g_hT[(size_t)BATCH * EE * FOUT * NN];

// ---------------------------------------------------------------- helpers ---
__device__ __forceinline__ uint32_t smem_u32(const void* p) {
    uint32_t a;
    asm("{ .reg .u64 t; cvta.to.shared.u64 t, %1; cvt.u32.u64 %0, t; }" : "=r"(a) : "l"(p));
    return a;
}
__device__ __forceinline__ uint32_t to_tf32(float x) {
    uint32_t u;
    asm("cvt.rna.tf32.f32 %0, %1;" : "=r"(u) : "f"(x));
    return u;
}
__device__ __forceinline__ float round_tf32(float x) { return __uint_as_float(to_tf32(x)); }

__device__ __forceinline__ void mma_tf32(float* d,
    uint32_t a0, uint32_t a1, uint32_t a2, uint32_t a3, uint32_t b0, uint32_t b1) {
    asm volatile(
        "mma.sync.aligned.m16n8k8.row.col.f32.tf32.tf32.f32 "
        "{%0,%1,%2,%3}, {%4,%5,%6,%7}, {%8,%9}, {%0,%1,%2,%3};"
        : "+f"(d[0]), "+f"(d[1]), "+f"(d[2]), "+f"(d[3])
        : "r"(a0), "r"(a1), "r"(a2), "r"(a3), "r"(b0), "r"(b1));
}
#define CP_COMMIT() asm volatile("cp.async.commit_group;" ::: "memory")
#define CP_WAIT1()  asm volatile("cp.async.wait_group 1;" ::: "memory")

__device__ __forceinline__ void cp16(float* s, const float* g) {
    asm volatile("cp.async.cg.shared.global [%0], [%1], 16;"
                 :: "r"(smem_u32(s)), "l"(g) : "memory");
}

// --- tile loaders (256 threads) ---
// normal K-major tile: ROWS x 32 floats, padded stride LDN
template<int ROWS>
__device__ __forceinline__ void load_n(const float* __restrict__ g, int ld, float* s, int tid) {
    #pragma unroll
    for (int i = 0; i < ROWS / 32; i++) {
        int idx = i * 256 + tid, r = idx >> 3, c = (idx & 7) * 4;
        cp16(s + r * LDN + c, g + (size_t)r * ld + c);
    }
}
// transposed tile: 32 rows (k) x COLS, padded stride LDS
template<int COLS, int LDS>
__device__ __forceinline__ void load_t(const float* __restrict__ g, int ld, float* s, int tid) {
    const int CPR = COLS / 4;              // 16B chunks per row
    #pragma unroll
    for (int i = 0; i < (32 * CPR) / 256; i++) {
        int idx = i * 256 + tid, r = idx / CPR, c = (idx % CPR) * 4;
        cp16(s + r * LDS + c, g + (size_t)r * ld + c);
    }
}

// --- one BK=32 chunk, CTA tile 128x256, warp tile 64x64 (wm in 0..1, wo in 0..3)
template<bool AT, bool CA, bool BT, bool CB, int LDA, int LDB>
__device__ __forceinline__ void compute_chunk(const float* __restrict__ As,
                                              const float* __restrict__ Bs,
                                              int wm, int wo, int lane, float* acc) {
    const int g = lane >> 2, t = lane & 3;
    #pragma unroll
    for (int ks = 0; ks < 4; ks++) {
        const int k0 = ks * 8;
        uint32_t af[4][4];
        #pragma unroll
        for (int mf = 0; mf < 4; mf++) {
            int r = wm * 64 + mf * 16 + g;
            float v0, v1, v2, v3;
            if (AT) {
                v0 = As[(k0 + t) * LDA + r];     v1 = As[(k0 + t) * LDA + r + 8];
                v2 = As[(k0 + t + 4) * LDA + r]; v3 = As[(k0 + t + 4) * LDA + r + 8];
            } else {
                const float* p0 = As + r * LDA + k0 + t;
                const float* p1 = As + (r + 8) * LDA + k0 + t;
                v0 = p0[0]; v1 = p1[0]; v2 = p0[4]; v3 = p1[4];
            }
            if (CA) { af[mf][0]=to_tf32(v0); af[mf][1]=to_tf32(v1); af[mf][2]=to_tf32(v2); af[mf][3]=to_tf32(v3); }
            else    { af[mf][0]=__float_as_uint(v0); af[mf][1]=__float_as_uint(v1);
                      af[mf][2]=__float_as_uint(v2); af[mf][3]=__float_as_uint(v3); }
        }
        uint32_t bf[8][2];
        #pragma unroll
        for (int nf = 0; nf < 8; nf++) {
            int r = wo * 64 + nf * 8 + g;
            float v0, v1;
            if (BT) { v0 = Bs[(k0 + t) * LDB + r]; v1 = Bs[(k0 + t + 4) * LDB + r]; }
            else    { const float* p = Bs + r * LDB + k0 + t; v0 = p[0]; v1 = p[4]; }
            if (CB) { bf[nf][0] = to_tf32(v0); bf[nf][1] = to_tf32(v1); }
            else    { bf[nf][0] = __float_as_uint(v0); bf[nf][1] = __float_as_uint(v1); }
        }
        #pragma unroll
        for (int mf = 0; mf < 4; mf++)
            #pragma unroll
            for (int nf = 0; nf < 8; nf++)
                mma_tf32(acc + (mf * 8 + nf) * 4, af[mf][0], af[mf][1], af[mf][2], af[mf][3],
                         bf[nf][0], bf[nf][1]);
    }
}

__device__ __forceinline__ void zero_acc(float* acc) {
    #pragma unroll
    for (int i = 0; i < 128; i++) acc[i] = 0.f;
}

// ---------------------------------------------------------------------------
// k1: hT[b,e,o,n] = sum_f W_e[f,o] * X[b,n,f] + b_adj[e,o]
//     CTA tile: M=128 (o), N=256 (n); 16 chunks (8 per e); A read transposed.
// ---------------------------------------------------------------------------
__global__ __launch_bounds__(256) void k1_ht(
    const float* __restrict__ X, const float* __restrict__ W_adj,
    const float* __restrict__ b_adj)
{
    extern __shared__ float sm[];
    const int tid = threadIdx.x, lane = tid & 31, wid = tid >> 5;
    const int wm = wid & 1, wo = wid >> 1;
    const int o0 = (blockIdx.x & 1) * 128, n0 = (blockIdx.x >> 1) * 256;
    const int b = blockIdx.y;

    const float* Bm = X + ((size_t)b * NN + n0) * FIN;
    float acc[128];
    zero_acc(acc);

    const int C = 16;
    // A chunk c: W_adj[e][f = kc*32 + r][o0 + col], e=c>>3, kc=c&7; rows = f, ld = FOUT
    #define K1_A(c) (W_adj + (size_t)((c) >> 3) * FIN * FOUT + (size_t)(((c) & 7) * BK) * FOUT + o0)
    #define K1_B(c) (Bm + ((c) & 7) * BK)
    #define K1_LD(c, s)  do {                                              \
        load_t<128, LDT1>(K1_A(c), FOUT, sm + (s) * K1_STAGE, tid);        \
        load_n<256>(K1_B(c), FIN, sm + (s) * K1_STAGE + K1_AF, tid);       \
        CP_COMMIT(); } while (0)

    K1_LD(0, 0);
    K1_LD(1, 1);

    const int g = lane >> 2, t = lane & 3;
    for (int c = 0; c < C; c++) {
        CP_WAIT1();
        __syncthreads();
        if (c + 2 < C) K1_LD(c + 2, (c + 2) % NSTAGE); else CP_COMMIT();
        const float* st = sm + (c % NSTAGE) * K1_STAGE;
        compute_chunk<true, true, false, true, LDT1, LDN>(st, st + K1_AF, wm, wo, lane, acc);

        if ((c & 7) == 7) {
            int e = c >> 3;
            #pragma unroll
            for (int mf = 0; mf < 4; mf++) {
                int r0 = o0 + wm * 64 + mf * 16 + g;
                float bias0 = b_adj[e * FOUT + r0];
                float bias1 = b_adj[e * FOUT + r0 + 8];
                #pragma unroll
                for (int nf = 0; nf < 8; nf++) {
                    int cc = n0 + wo * 64 + nf * 8 + 2 * t;
                    float* a4 = acc + (mf * 8 + nf) * 4;
                    float* d0 = g_hT + (((size_t)(b * EE + e) * FOUT) + r0) * NN + cc;
                    float* d1 = g_hT + (((size_t)(b * EE + e) * FOUT) + r0 + 8) * NN + cc;
                    *(float2*)d0 = make_float2(round_tf32(a4[0] + bias0), round_tf32(a4[1] + bias0));
                    *(float2*)d1 = make_float2(round_tf32(a4[2] + bias1), round_tf32(a4[3] + bias1));
                }
            }
            zero_acc(acc);
        }
    }
}

// ---------------------------------------------------------------------------
// k2: out[b,m,o] = relu( sum_e adj[b,e,m,:] . hT[b,e,o,:]
//                      + sum_f X[b,m,f] * W2[f,o] + b2[o] )
//     CTA tile: M=128 (m), N=256 (o = full FOUT); 40 chained chunks.
// ---------------------------------------------------------------------------
__global__ __launch_bounds__(256) void k2_main(
    const float* __restrict__ adj, const float* __restrict__ X,
    const float* __restrict__ W2, const float* __restrict__ b2,
    float* __restrict__ out)
{
    extern __shared__ float sm[];
    const int tid = threadIdx.x, lane = tid & 31, wid = tid >> 5;
    const int wm = wid & 1, wo = wid >> 1;
    const int m0 = blockIdx.x * 128;
    const int b = blockIdx.y;

    const float* adjb = adj + (size_t)b * EE * NN * NN + (size_t)m0 * NN;
    const float* hTb  = g_hT + (size_t)b * EE * FOUT * NN;
    const float* Xb   = X + ((size_t)b * NN + m0) * FIN;

    float acc[128];
    zero_acc(acc);

    const int C = 40;  // 16 (e=0) + 16 (e=1) + 8 (lin2)
    #define K2_LD(c, s) do {                                                      \
        float* sA = sm + (s) * K2_STAGE;                                          \
        float* sB = sA + K2_AF;                                                   \
        if ((c) < 32) {                                                           \
            int e_ = (c) >> 4, kc_ = (c) & 15;                                    \
            load_n<128>(adjb + (size_t)e_ * NN * NN + kc_ * BK, NN, sA, tid);     \
            load_n<256>(hTb + (size_t)e_ * FOUT * NN + kc_ * BK, NN, sB, tid);    \
        } else {                                                                  \
            int kc_ = (c) - 32;                                                   \
            load_n<128>(Xb + kc_ * BK, FIN, sA, tid);                             \
            load_t<256, LDT2>(W2 + (size_t)(kc_ * BK) * FOUT, FOUT, sB, tid);     \
        }                                                                         \
        CP_COMMIT(); } while (0)

    K2_LD(0, 0);
    K2_LD(1, 1);

    for (int c = 0; c < C; c++) {
        CP_WAIT1();
        __syncthreads();
        if (c + 2 < C) K2_LD(c + 2, (c + 2) % NSTAGE); else CP_COMMIT();
        const float* st = sm + (c % NSTAGE) * K2_STAGE;
        if (c < 32)
            compute_chunk<false, true, false, false, LDN, LDN>(st, st + K2_AF, wm, wo, lane, acc);
        else
            compute_chunk<false, true, true, true, LDN, LDT2>(st, st + K2_AF, wm, wo, lane, acc);
    }

    // epilogue: + b2[o], relu, store
    const int g = lane >> 2, t = lane & 3;
    #pragma unroll
    for (int mf = 0; mf < 4; mf++) {
        int r0 = m0 + wm * 64 + mf * 16 + g;
        #pragma unroll
        for (int nf = 0; nf < 8; nf++) {
            int cc = wo * 64 + nf * 8 + 2 * t;
            float bx = b2[cc], by = b2[cc + 1];
            float* a4 = acc + (mf * 8 + nf) * 4;
            float* d0 = out + ((size_t)b * NN + r0) * FOUT + cc;
            float* d1 = out + ((size_t)b * NN + r0 + 8) * FOUT + cc;
            *(float2*)d0 = make_float2(fmaxf(a4[0] + bx, 0.f), fmaxf(a4[1] + by, 0.f));
            *(float2*)d1 = make_float2(fmaxf(a4[2] + bx, 0.f), fmaxf(a4[3] + by, 0.f));
        }
    }
}

// ---------------------------------------------------------------------------
extern "C" void kernel_launch(void* const* d_in, const int* in_sizes, int n_in,
                              void* d_out, int out_size)
{
    const float* n_tensor   = (const float*)d_in[0];  // [32,512,256]
    const float* adj_tensor = (const float*)d_in[1];  // [32,2,512,512]
    const float* W_adj      = (const float*)d_in[2];  // [2,256,256]
    const float* b_adj      = (const float*)d_in[3];  // [2,256]
    const float* W2         = (const float*)d_in[4];  // [256,256]
    const float* b2         = (const float*)d_in[5];  // [256]
    float*       out        = (float*)d_out;          // [32,512,256]

    cudaFuncSetAttribute(k1_ht,   cudaFuncAttributeMaxDynamicSharedMemorySize, K1_SMEM);
    cudaFuncSetAttribute(k2_main, cudaFuncAttributeMaxDynamicSharedMemorySize, K2_SMEM);

    k1_ht<<<dim3(4, BATCH), 256, K1_SMEM>>>(n_tensor, W_adj, b_adj);
    k2_main<<<dim3(4, BATCH), 256, K2_SMEM>>>(adj_tensor, n_tensor, W2, b2, out);
}